// round 17
// baseline (speedup 1.0000x reference)
#include <cuda_runtime.h>
#include <cuda_bf16.h>
#include <cstdint>

// Problem dims (fixed by reference)
#define HWDIM 196
#define BATCH 64
#define DDIM  768
#define EDIM  256
#define CDIM  10
#define M1    (BATCH * HWDIM)   // 12544 rows (b,h)

typedef unsigned long long ull;

// ---------------- f32x2 helpers ----------------
#define FMA2(acc, a, b) \
    asm("fma.rn.f32x2 %0, %1, %2, %0;" : "+l"(acc) : "l"(a), "l"(b))
#define PACK2(p, v) \
    asm("mov.b64 %0, {%1, %1};" : "=l"(p) : "f"(v))
#define UNPACK2(lo, hi, p) \
    asm("mov.b64 {%0, %1}, %2;" : "=f"(lo), "=f"(hi) : "l"(p))

__device__ __forceinline__ void cp16s(uint32_t smem_dst, const void* gsrc) {
    asm volatile("cp.async.cg.shared.global [%0], [%1], 16;" :: "r"(smem_dst), "l"(gsrc));
}
#define CP_COMMIT() asm volatile("cp.async.commit_group;")
#define CP_WAIT0()  asm volatile("cp.async.wait_group 0;")

__device__ __forceinline__ uint32_t smem_u32(const void* p) {
    uint32_t a;
    asm("{ .reg .u64 t; cvta.to.shared.u64 t, %1; cvt.u32.u64 %0, t; }"
        : "=r"(a) : "l"(p));
    return a;
}

// ---------------- warp-level bf16 MMA (sm_80+ PTX) -------------------------
#define LDSM_X4(r0, r1, r2, r3, addr) \
    asm volatile("ldmatrix.sync.aligned.m8n8.x4.shared.b16 {%0,%1,%2,%3}, [%4];" \
                 : "=r"(r0), "=r"(r1), "=r"(r2), "=r"(r3) : "r"(addr))

#define MMA16816(d, a0, a1, a2, a3, b0, b1) \
    asm volatile("mma.sync.aligned.m16n8k16.row.col.f32.bf16.bf16.f32 " \
                 "{%0,%1,%2,%3}, {%4,%5,%6,%7}, {%8,%9}, {%0,%1,%2,%3};" \
                 : "+f"((d)[0]), "+f"((d)[1]), "+f"((d)[2]), "+f"((d)[3]) \
                 : "r"(a0), "r"(a1), "r"(a2), "r"(a3), "r"(b0), "r"(b1))

// ---------------- scratch (static device globals) ----------------
__device__ float          g_S[(size_t)M1 * EDIM];        // sign pattern
__device__ __nv_bfloat16  g_Xhi[(size_t)M1 * DDIM];
__device__ __nv_bfloat16  g_Xlo[(size_t)M1 * DDIM];
__device__ __nv_bfloat16  g_Whi[(size_t)EDIM * DDIM];
__device__ __nv_bfloat16  g_Wlo[(size_t)EDIM * DDIM];

// ---------------------------------------------------------------------------
// k0: split fp32 -> bf16 hi + bf16 lo (residual).
// ---------------------------------------------------------------------------
__global__ void k0_split_x(const float* __restrict__ X)
{
    int i = blockIdx.x * 256 + threadIdx.x;   // float4 index, grid exact
    float4 v = reinterpret_cast<const float4*>(X)[i];
    __nv_bfloat162 h01 = __floats2bfloat162_rn(v.x, v.y);
    __nv_bfloat162 h23 = __floats2bfloat162_rn(v.z, v.w);
    float r0 = v.x - __bfloat162float(h01.x);
    float r1 = v.y - __bfloat162float(h01.y);
    float r2 = v.z - __bfloat162float(h23.x);
    float r3 = v.w - __bfloat162float(h23.y);
    __nv_bfloat162 l01 = __floats2bfloat162_rn(r0, r1);
    __nv_bfloat162 l23 = __floats2bfloat162_rn(r2, r3);
    reinterpret_cast<__nv_bfloat162*>(g_Xhi)[2 * i + 0] = h01;
    reinterpret_cast<__nv_bfloat162*>(g_Xhi)[2 * i + 1] = h23;
    reinterpret_cast<__nv_bfloat162*>(g_Xlo)[2 * i + 0] = l01;
    reinterpret_cast<__nv_bfloat162*>(g_Xlo)[2 * i + 1] = l23;
}

__global__ void k0_split_w(const float* __restrict__ W)
{
    int i = blockIdx.x * 256 + threadIdx.x;
    float4 v = reinterpret_cast<const float4*>(W)[i];
    __nv_bfloat162 h01 = __floats2bfloat162_rn(v.x, v.y);
    __nv_bfloat162 h23 = __floats2bfloat162_rn(v.z, v.w);
    float r0 = v.x - __bfloat162float(h01.x);
    float r1 = v.y - __bfloat162float(h01.y);
    float r2 = v.z - __bfloat162float(h23.x);
    float r3 = v.w - __bfloat162float(h23.y);
    __nv_bfloat162 l01 = __floats2bfloat162_rn(r0, r1);
    __nv_bfloat162 l23 = __floats2bfloat162_rn(r2, r3);
    reinterpret_cast<__nv_bfloat162*>(g_Whi)[2 * i + 0] = h01;
    reinterpret_cast<__nv_bfloat162*>(g_Whi)[2 * i + 1] = h23;
    reinterpret_cast<__nv_bfloat162*>(g_Wlo)[2 * i + 0] = l01;
    reinterpret_cast<__nv_bfloat162*>(g_Wlo)[2 * i + 1] = l23;
}

// ---------------------------------------------------------------------------
// Kernel 1 (HMMA, R10 config = best measured 111.4us): S = sign(X@W^T + b),
// bf16 3-product split [Xhi*Whi | Xhi*Wlo | Xlo*Whi], 36 K64 chunks.
// Block 128(M)x64(N), 4 warps, 2-stage cp.async, 144B-pitch smem.
// Borderline |z| < 0.05 refined with SEQUENTIAL-fmaf fp32 dot (R12 fix).
// grid (4, 98), 128 threads, dyn smem 55296 B.
// ---------------------------------------------------------------------------
#define K1_SMEM 55296
#define APITCH  144               // 72 bf16 per row (64 data + 8 pad)
#define A_OFF(buf) ((buf) * 18432)
#define B_OFF(buf) (36864 + (buf) * 9216)

__global__ __launch_bounds__(128) void k1_mma(
    const float* __restrict__ X, const float* __restrict__ W,
    const float* __restrict__ bias)
{
    extern __shared__ char smem[];
    const uint32_t sbase = smem_u32(smem);
    const int tid  = threadIdx.x;
    const int w    = tid >> 5;
    const int lane = tid & 31;
    const int m0   = blockIdx.y * 128;
    const int n0   = blockIdx.x * 64;

    const __nv_bfloat16* Aseg[3] = { g_Xhi, g_Xhi, g_Xlo };
    const __nv_bfloat16* Bseg[3] = { g_Whi, g_Wlo, g_Whi };

    auto issue = [&](int t, int buf) {
        const int seg = t / 12;
        const int kk0 = (t % 12) * 64;
        const __nv_bfloat16* Ab = Aseg[seg];
        const __nv_bfloat16* Bb = Bseg[seg];
        const uint32_t a_s = sbase + A_OFF(buf);
        const uint32_t b_s = sbase + B_OFF(buf);
        #pragma unroll
        for (int l = 0; l < 8; l++) {
            int s = tid + l * 128;
            int r = s >> 3, c = s & 7;
            cp16s(a_s + r * APITCH + c * 16,
                  Ab + (size_t)(m0 + r) * DDIM + kk0 + c * 8);
        }
        #pragma unroll
        for (int l = 0; l < 4; l++) {
            int s = tid + l * 128;
            int r = s >> 3, c = s & 7;
            cp16s(b_s + r * APITCH + c * 16,
                  Bb + (size_t)(n0 + r) * DDIM + kk0 + c * 8);
        }
        CP_COMMIT();
    };

    issue(0, 0);

    float acc[2][8][4];
    #pragma unroll
    for (int i = 0; i < 2; i++)
        #pragma unroll
        for (int j = 0; j < 8; j++)
            #pragma unroll
            for (int c = 0; c < 4; c++) acc[i][j][c] = 0.f;

    const int lrow = lane & 15;
    const int lcol = (lane >> 4) * 16;

    for (int t = 0; t < 36; t++) {
        CP_WAIT0();
        __syncthreads();
        if (t < 35) issue(t + 1, (t + 1) & 1);

        const uint32_t a_s = sbase + A_OFF(t & 1);
        const uint32_t b_s = sbase + B_OFF(t & 1);

        #pragma unroll
        for (int kk = 0; kk < 4; kk++) {
            const uint32_t kb = kk * 32;
            uint32_t ra[2][4], rb[4][4];
            #pragma unroll
            for (int i = 0; i < 2; i++) {
                uint32_t ad = a_s + (w * 32 + i * 16 + lrow) * APITCH + kb + lcol;
                LDSM_X4(ra[i][0], ra[i][1], ra[i][2], ra[i][3], ad);
            }
            #pragma unroll
            for (int j2 = 0; j2 < 4; j2++) {
                uint32_t bd = b_s + (j2 * 16 + lrow) * APITCH + kb + lcol;
                LDSM_X4(rb[j2][0], rb[j2][1], rb[j2][2], rb[j2][3], bd);
            }
            #pragma unroll
            for (int i = 0; i < 2; i++)
                #pragma unroll
                for (int j2 = 0; j2 < 4; j2++) {
                    MMA16816(acc[i][2 * j2 + 0],
                             ra[i][0], ra[i][1], ra[i][2], ra[i][3],
                             rb[j2][0], rb[j2][2]);
                    MMA16816(acc[i][2 * j2 + 1],
                             ra[i][0], ra[i][1], ra[i][2], ra[i][3],
                             rb[j2][1], rb[j2][3]);
                }
        }
    }

    // ---- epilogue: bias + sign + borderline mask -------------------------
    const int mrow = lane >> 2;
    const int ncol = (lane & 3) * 2;
    ull border = 0ull;

    #pragma unroll
    for (int i = 0; i < 2; i++) {
        #pragma unroll
        for (int j = 0; j < 8; j++) {
            const int n = n0 + j * 8 + ncol;
            const float b0 = __ldg(&bias[n]);
            const float b1 = __ldg(&bias[n + 1]);
            float v0 = acc[i][j][0] + b0;
            float v1 = acc[i][j][1] + b1;
            float v2 = acc[i][j][2] + b0;
            float v3 = acc[i][j][3] + b1;
            if (fabsf(v0) < 0.05f) border |= 1ull << (i * 32 + j * 4 + 0);
            if (fabsf(v1) < 0.05f) border |= 1ull << (i * 32 + j * 4 + 1);
            if (fabsf(v2) < 0.05f) border |= 1ull << (i * 32 + j * 4 + 2);
            if (fabsf(v3) < 0.05f) border |= 1ull << (i * 32 + j * 4 + 3);
            const int mA = m0 + w * 32 + i * 16 + mrow;
            float2 oA = make_float2(v0 > 0.f ? 1.f : 0.f, v1 > 0.f ? 1.f : 0.f);
            float2 oB = make_float2(v2 > 0.f ? 1.f : 0.f, v3 > 0.f ? 1.f : 0.f);
            *reinterpret_cast<float2*>(&g_S[(size_t)mA * EDIM + n]) = oA;
            *reinterpret_cast<float2*>(&g_S[(size_t)(mA + 8) * EDIM + n]) = oB;
        }
    }

    // ---- exact fp32 refinement: STRICT sequential fmaf chain (R12 fix) ---
    while (border) {
        int q = __ffsll(border) - 1;
        border &= border - 1;
        int i = q >> 5, j = (q >> 2) & 7, c = q & 3;
        int m = m0 + w * 32 + i * 16 + mrow + 8 * (c >> 1);
        int n = n0 + j * 8 + ncol + (c & 1);
        const float* xrow = X + (size_t)m * DDIM;
        const float* wrow = W + (size_t)n * DDIM;
        float s = 0.f;
        for (int d = 0; d < DDIM; d++)
            s = fmaf(xrow[d], wrow[d], s);
        float v = s + __ldg(&bias[n]);
        g_S[(size_t)m * EDIM + n] = (v > 0.f) ? 1.f : 0.f;
    }
}

// ---------------------------------------------------------------------------
// Kernel 2 (FUSED, 2 batches/block): per (d-slice, e-half, b-pair) compute
// T-tiles [128e x 64d] for TWO batches in regs (f32x2), then contract with
// lm_w sharing each LW load across both batches (halves LW L2 traffic),
// atomicAdd into out. X staged pre-duplicated as (x,x) f32x2 pairs -> no
// PACK in the inner loop. grid (12, 2, 32), 128 thr, dyn smem 67584 B.
// ---------------------------------------------------------------------------
#define K2_PITCH 132                         // f32 per smem row (S and Xd)
#define K2_SROW  (16 * K2_PITCH)             // f32 per (buf,b) S tile
#define K2_SOFF(buf, b)  (((buf) * 2 + (b)) * K2_SROW)
#define K2_XBASE (4 * K2_SROW)
#define K2_XOFF(buf, b)  (K2_XBASE + ((buf) * 2 + (b)) * K2_SROW)
#define K2_SMEM  (8 * K2_SROW * 4)           // 67584 B

__global__ __launch_bounds__(128) void k2_fused(
    const float* __restrict__ X, const float* __restrict__ LW,
    float* __restrict__ out)
{
    extern __shared__ char smem[];
    float* sm = reinterpret_cast<float*>(smem);

    const int tid = threadIdx.x;
    const int tx  = tid & 7;                 // d: tx*8 .. +7
    const int ty  = tid >> 3;                // e: ty*8 .. +7  (0..15)
    const int b0  = blockIdx.z * 2;
    const int e0  = blockIdx.y * 128;
    const int d0  = blockIdx.x * 64;

    const float* Sb[2] = { &g_S[(size_t)b0 * HWDIM * EDIM],
                           &g_S[(size_t)(b0 + 1) * HWDIM * EDIM] };
    const float* Xb[2] = { &X[(size_t)b0 * HWDIM * DDIM],
                           &X[(size_t)(b0 + 1) * HWDIM * DDIM] };

    // --- staging helpers ---
    auto issueS = [&](int k0, int nb) {
        #pragma unroll
        for (int bb = 0; bb < 2; bb++) {
            float* dst = sm + K2_SOFF(nb, bb);
            uint32_t du = smem_u32(dst);
            #pragma unroll
            for (int l = 0; l < 4; l++) {
                int s  = tid + l * 128;
                int h  = s >> 5;
                int e4 = (s & 31) * 4;
                int hh = k0 + h;
                if (hh < HWDIM)
                    cp16s(du + (h * K2_PITCH + e4) * 4,
                          Sb[bb] + (size_t)hh * EDIM + e0 + e4);
                else
                    *reinterpret_cast<float4*>(&dst[h * K2_PITCH + e4]) =
                        make_float4(0.f, 0.f, 0.f, 0.f);
            }
        }
        CP_COMMIT();
    };

    float4 xa[2][2];
    auto loadX = [&](int k0) {
        #pragma unroll
        for (int bb = 0; bb < 2; bb++)
            #pragma unroll
            for (int l = 0; l < 2; l++) {
                int s  = tid + l * 128;
                int h  = s >> 4;
                int d4 = (s & 15) * 4;
                int hh = k0 + h;
                xa[bb][l] = (hh < HWDIM)
                    ? *reinterpret_cast<const float4*>(
                          &Xb[bb][(size_t)hh * DDIM + d0 + d4])
                    : make_float4(0.f, 0.f, 0.f, 0.f);
            }
    };
    auto storeX = [&](int nb) {
        #pragma unroll
        for (int bb = 0; bb < 2; bb++) {
            float* dst = sm + K2_XOFF(nb, bb);
            #pragma unroll
            for (int l = 0; l < 2; l++) {
                int s  = tid + l * 128;
                int h  = s >> 4;
                int d4 = (s & 15) * 4;
                ull p0, p1, p2, p3;
                PACK2(p0, xa[bb][l].x);
                PACK2(p1, xa[bb][l].y);
                PACK2(p2, xa[bb][l].z);
                PACK2(p3, xa[bb][l].w);
                ull* q = reinterpret_cast<ull*>(&dst[h * K2_PITCH + 2 * d4]);
                q[0] = p0; q[1] = p1; q[2] = p2; q[3] = p3;
            }
        }
    };

    // prologue: stage tile 0 into buf 0
    issueS(0, 0);
    loadX(0);
    storeX(0);

    ull acc2[2][4][8];
    #pragma unroll
    for (int bb = 0; bb < 2; bb++)
        #pragma unroll
        for (int i = 0; i < 4; i++)
            #pragma unroll
            for (int j = 0; j < 8; j++) acc2[bb][i][j] = 0ull;

    int buf = 0;
    const int NT = (HWDIM + 15) / 16;   // 13
    for (int t = 0; t < NT; t++) {
        CP_WAIT0();
        __syncthreads();
        if (t < NT - 1) { issueS((t + 1) * 16, buf ^ 1); loadX((t + 1) * 16); }

        #pragma unroll
        for (int kk = 0; kk < 16; kk++) {
            #pragma unroll
            for (int bb = 0; bb < 2; bb++) {
                const float* srow = sm + K2_SOFF(buf, bb) + kk * K2_PITCH;
                const float* xrow = sm + K2_XOFF(buf, bb) + kk * K2_PITCH;
                ulonglong2 a01 = *reinterpret_cast<const ulonglong2*>(&srow[ty * 8]);
                ulonglong2 a23 = *reinterpret_cast<const ulonglong2*>(&srow[ty * 8 + 4]);
                ull ra2[4] = { a01.x, a01.y, a23.x, a23.y };
                ull rb2[8];
                #pragma unroll
                for (int u = 0; u < 4; u++) {
                    ulonglong2 q = *reinterpret_cast<const ulonglong2*>(
                        &xrow[tx * 16 + 4 * u]);
                    rb2[2 * u + 0] = q.x;
                    rb2[2 * u + 1] = q.y;
                }
                #pragma unroll
                for (int i = 0; i < 4; i++)
                    #pragma unroll
                    for (int j = 0; j < 8; j++)
                        FMA2(acc2[bb][i][j], ra2[i], rb2[j]);
            }
        }

        if (t < NT - 1) storeX(buf ^ 1);
        __syncthreads();
        buf ^= 1;
    }

    // ---- fused epilogue: LW loads shared across both batches -------------
    float p0c[CDIM], p1c[CDIM];
    #pragma unroll
    for (int c = 0; c < CDIM; c++) { p0c[c] = 0.f; p1c[c] = 0.f; }

    #pragma unroll
    for (int i = 0; i < 4; i++) {
        float e0lo[8], e0hi[8], e1lo[8], e1hi[8];
        #pragma unroll
        for (int j = 0; j < 8; j++) {
            UNPACK2(e0lo[j], e0hi[j], acc2[0][i][j]);
            UNPACK2(e1lo[j], e1hi[j], acc2[1][i][j]);
        }
        const int eA = e0 + ty * 8 + 2 * i;     // even e
        #pragma unroll
        for (int c = 0; c < CDIM; c++) {
            const float* rA = &LW[((size_t)eA * CDIM + c) * DDIM + d0 + tx * 8];
            const float* rB = &LW[((size_t)(eA + 1) * CDIM + c) * DDIM + d0 + tx * 8];
            float4 a0 = *reinterpret_cast<const float4*>(rA + 0);
            float4 a1 = *reinterpret_cast<const float4*>(rA + 4);
            float4 bq0 = *reinterpret_cast<const float4*>(rB + 0);
            float4 bq1 = *reinterpret_cast<const float4*>(rB + 4);
            float s0 = 0.f, s1 = 0.f;
            s0 += e0lo[0] * a0.x + e0lo[1] * a0.y + e0lo[2] * a0.z + e0lo[3] * a0.w;
            s0 += e0lo[4] * a1.x + e0lo[5] * a1.y + e0lo[6] * a1.z + e0lo[7] * a1.w;
            s0 += e0hi[0] * bq0.x + e0hi[1] * bq0.y + e0hi[2] * bq0.z + e0hi[3] * bq0.w;
            s0 += e0hi[4] * bq1.x + e0hi[5] * bq1.y + e0hi[6] * bq1.z + e0hi[7] * bq1.w;
            s1 += e1lo[0] * a0.x + e1lo[1] * a0.y + e1lo[2] * a0.z + e1lo[3] * a0.w;
            s1 += e1lo[4] * a1.x + e1lo[5] * a1.y + e1lo[6] * a1.z + e1lo[7] * a1.w;
            s1 += e1hi[0] * bq0.x + e1hi[1] * bq0.y + e1hi[2] * bq0.z + e1hi[3] * bq0.w;
            s1 += e1hi[4] * bq1.x + e1hi[5] * bq1.y + e1hi[6] * bq1.z + e1hi[7] * bq1.w;
            p0c[c] += s0;
            p1c[c] += s1;
        }
    }

    // ---- two block reductions (reuse smem), atomicAdd per batch ----------
    const float scale = 1.0f / ((float)HWDIM * (float)EDIM);
    float* red = sm;
    __syncthreads();
    #pragma unroll
    for (int c = 0; c < CDIM; c++) red[c * 128 + tid] = p0c[c];
    __syncthreads();
    #pragma unroll
    for (int off = 64; off >= 1; off >>= 1) {
        if (tid < off) {
            #pragma unroll
            for (int c = 0; c < CDIM; c++)
                red[c * 128 + tid] += red[c * 128 + tid + off];
        }
        __syncthreads();
    }
    if (tid < CDIM) atomicAdd(&out[b0 * CDIM + tid], red[tid * 128] * scale);
    __syncthreads();
    #pragma unroll
    for (int c = 0; c < CDIM; c++) red[c * 128 + tid] = p1c[c];
    __syncthreads();
    #pragma unroll
    for (int off = 64; off >= 1; off >>= 1) {
        if (tid < off) {
            #pragma unroll
            for (int c = 0; c < CDIM; c++)
                red[c * 128 + tid] += red[c * 128 + tid + off];
        }
        __syncthreads();
    }
    if (tid < CDIM)
        atomicAdd(&out[(b0 + 1) * CDIM + tid], red[tid * 128] * scale);
}

// ---------------------------------------------------------------------------
__global__ void k_zero(float* __restrict__ out)
{
    int p = blockIdx.x * blockDim.x + threadIdx.x;
    if (p < BATCH * CDIM) out[p] = 0.f;
}

// ---------------------------------------------------------------------------
extern "C" void kernel_launch(void* const* d_in, const int* in_sizes, int n_in,
                              void* d_out, int out_size)
{
    const float* X   = (const float*)d_in[0];   // (64,196,768)
    const float* AGW = (const float*)d_in[1];   // (256,768)
    const float* AGB = (const float*)d_in[2];   // (256,)
    const float* LW  = (const float*)d_in[3];   // (2560,768)
    float* out = (float*)d_out;                 // (64,10)

    cudaFuncSetAttribute(k1_mma, cudaFuncAttributeMaxDynamicSharedMemorySize,
                         K1_SMEM);
    cudaFuncSetAttribute(k2_fused, cudaFuncAttributeMaxDynamicSharedMemorySize,
                         K2_SMEM);

    k0_split_x<<<(M1 * DDIM / 4) / 256, 256>>>(X);          // 9408 blocks
    k0_split_w<<<(EDIM * DDIM / 4) / 256, 256>>>(AGW);      // 192 blocks
    k_zero<<<3, 256>>>(out);
    k1_mma<<<dim3(EDIM / 64, M1 / 128), 128, K1_SMEM>>>(X, AGW, AGB);
    k2_fused<<<dim3(DDIM / 64, 2, BATCH / 2), 128, K2_SMEM>>>(X, LW, out);
}